// round 2
// baseline (speedup 1.0000x reference)
#include <cuda_runtime.h>
#include <cuda_bf16.h>

#define N_NODES 50000
#define N_EDGES 800000
#define NODE_DIM 128
#define IN_CH 64
#define OUT_CH 16
#define N_GRAPHS 512
#define N_LAYERS 5

// ---------------- scratch (device globals; 16B-aligned for float4) ----------
__device__ __align__(16) float d_h[N_NODES * IN_CH];
__device__ __align__(16) float d_z[N_NODES * IN_CH];
__device__ __align__(16) float d_t[N_NODES * IN_CH];
__device__ __align__(16) double d_bnacc[N_LAYERS * 2 * IN_CH];
__device__ __align__(16) float d_bnsb[N_LAYERS * 2 * IN_CH];
__device__ __align__(16) float d_g[N_GRAPHS * IN_CH];
__device__ int d_idx64;      // 1 if edge_index/batch are int64, 0 if int32

// ---------------- dtype sniff: int64 arrays of small values have odd words 0 -
__global__ void detect_kernel(const unsigned int* __restrict__ ei_words) {
    __shared__ int any_nonzero;
    if (threadIdx.x == 0) any_nonzero = 0;
    __syncthreads();
    // sample 256 odd-position 32-bit words from the first 512 words
    unsigned w = ei_words[threadIdx.x * 2 + 1];
    if (w != 0u) atomicOr(&any_nonzero, 1);
    __syncthreads();
    if (threadIdx.x == 0) d_idx64 = (any_nonzero == 0) ? 1 : 0;
}

__device__ __forceinline__ int load_idx(const void* p, long long i) {
    if (d_idx64) return (int)((const long long*)p)[i];
    return ((const int*)p)[i];
}

// ---------------- zero init --------------------------------------------------
__global__ void zero_kernel() {
    int i = blockIdx.x * blockDim.x + threadIdx.x;
    if (i < N_GRAPHS * IN_CH) d_g[i] = 0.0f;
    if (i < N_LAYERS * 2 * IN_CH) d_bnacc[i] = 0.0;
}

// ---------------- GEMM: C[N,64] = act(A[N,K] @ W[K,64] + b) ------------------
// block: 256 threads, 64 rows x 64 cols; each thread 4x4 micro-tile.
template<int K, bool RELU, bool BNSTATS>
__global__ void gemm64(const float* __restrict__ A, const float* __restrict__ W,
                       const float* __restrict__ bias, float* __restrict__ Co,
                       float* __restrict__ C2, int Nrows, double* __restrict__ bnacc)
{
    __shared__ float As[64][66];       // pad 66: conflict-free column reads
    __shared__ float Ws[64][64];
    __shared__ float ssum[64];
    __shared__ float ssq[64];

    const int tid = threadIdx.x;
    const int tx = tid & 15;           // col group (4 cols)
    const int ty = tid >> 4;           // row group (4 rows)
    const int row0 = blockIdx.x * 64;

    float acc[4][4];
#pragma unroll
    for (int i = 0; i < 4; i++)
#pragma unroll
        for (int j = 0; j < 4; j++) acc[i][j] = 0.0f;

    for (int kc = 0; kc < K / 64; kc++) {
#pragma unroll
        for (int i = 0; i < 4; i++) {
            int f = tid + i * 256;
            int r = f >> 4, c4 = f & 15;
            int gr = row0 + r;
            float4 v = make_float4(0.f, 0.f, 0.f, 0.f);
            if (gr < Nrows)
                v = *(const float4*)(A + (size_t)gr * K + kc * 64 + c4 * 4);
            As[r][c4 * 4 + 0] = v.x;
            As[r][c4 * 4 + 1] = v.y;
            As[r][c4 * 4 + 2] = v.z;
            As[r][c4 * 4 + 3] = v.w;
        }
#pragma unroll
        for (int i = 0; i < 4; i++) {
            int f = tid + i * 256;
            int wr = f >> 4, c4 = f & 15;
            *(float4*)(&Ws[wr][c4 * 4]) =
                *(const float4*)(W + (size_t)(kc * 64 + wr) * 64 + c4 * 4);
        }
        __syncthreads();

#pragma unroll 8
        for (int k = 0; k < 64; k++) {
            float4 wv = *(const float4*)(&Ws[k][tx * 4]);
#pragma unroll
            for (int i = 0; i < 4; i++) {
                float a = As[ty * 4 + i][k];
                acc[i][0] += a * wv.x;
                acc[i][1] += a * wv.y;
                acc[i][2] += a * wv.z;
                acc[i][3] += a * wv.w;
            }
        }
        __syncthreads();
    }

    float4 bv = *(const float4*)(bias + tx * 4);
    float csum[4] = {0.f, 0.f, 0.f, 0.f};
    float csq[4] = {0.f, 0.f, 0.f, 0.f};

#pragma unroll
    for (int i = 0; i < 4; i++) {
        int gr = row0 + ty * 4 + i;
        float4 o;
        o.x = acc[i][0] + bv.x;
        o.y = acc[i][1] + bv.y;
        o.z = acc[i][2] + bv.z;
        o.w = acc[i][3] + bv.w;
        if (RELU) {
            o.x = fmaxf(o.x, 0.f); o.y = fmaxf(o.y, 0.f);
            o.z = fmaxf(o.z, 0.f); o.w = fmaxf(o.w, 0.f);
        }
        if (gr < Nrows) {
            *(float4*)(Co + (size_t)gr * 64 + tx * 4) = o;
            if (C2) *(float4*)(C2 + (size_t)gr * 64 + tx * 4) = o;
            if (BNSTATS) {
                csum[0] += o.x; csum[1] += o.y; csum[2] += o.z; csum[3] += o.w;
                csq[0] += o.x * o.x; csq[1] += o.y * o.y;
                csq[2] += o.z * o.z; csq[3] += o.w * o.w;
            }
        }
    }

    if (BNSTATS) {
        if (tid < 64) { ssum[tid] = 0.f; ssq[tid] = 0.f; }
        __syncthreads();
#pragma unroll
        for (int j = 0; j < 4; j++) {
            atomicAdd(&ssum[tx * 4 + j], csum[j]);
            atomicAdd(&ssq[tx * 4 + j], csq[j]);
        }
        __syncthreads();
        if (tid < 64) {
            atomicAdd(&bnacc[tid], (double)ssum[tid]);
            atomicAdd(&bnacc[64 + tid], (double)ssq[tid]);
        }
    }
}

// ---------------- edge scatter: z[dst] += h[src] (vector RED) ----------------
__global__ void scatter_kernel(const void* __restrict__ ei) {
    int t = blockIdx.x * blockDim.x + threadIdx.x;
    if (t >= N_EDGES * 16) return;
    int e = t >> 4;
    int v = t & 15;
    int src = load_idx(ei, e);
    int dst = load_idx(ei, (long long)N_EDGES + e);
    float4 val = *((const float4*)d_h + (size_t)src * 16 + v);
    float* addr = d_z + (size_t)dst * 64 + v * 4;
    asm volatile("red.global.add.v4.f32 [%0], {%1, %2, %3, %4};"
                 :: "l"(addr), "f"(val.x), "f"(val.y), "f"(val.z), "f"(val.w)
                 : "memory");
}

// ---------------- BN finalize: scale/bias from accumulated stats -------------
__global__ void bn_finalize(const double* __restrict__ acc,
                            const float* __restrict__ gamma,
                            const float* __restrict__ beta,
                            float* __restrict__ sb)
{
    int c = threadIdx.x;  // 64 threads
    double sum = acc[c];
    double sq = acc[64 + c];
    float mean = (float)(sum / (double)N_NODES);
    float var = (float)(sq / (double)N_NODES) - mean * mean;
    float sc = gamma[c] * rsqrtf(var + 1e-5f);
    sb[c] = sc;
    sb[64 + c] = beta[c] - mean * sc;
}

// ---------------- BN apply: h = z*scale+bias, z = h ---------------------------
__global__ void bn_apply(const float* __restrict__ sb) {
    int i = blockIdx.x * blockDim.x + threadIdx.x;   // over N*C/4 float4
    if (i >= N_NODES * 16) return;
    int c4 = i & 15;
    float4 s = *((const float4*)sb + c4);
    float4 b = *((const float4*)sb + 16 + c4);
    float4 v = *((const float4*)d_z + i);
    float4 r;
    r.x = v.x * s.x + b.x;
    r.y = v.y * s.y + b.y;
    r.z = v.z * s.z + b.z;
    r.w = v.w * s.w + b.w;
    *((float4*)d_h + i) = r;
    *((float4*)d_z + i) = r;   // z init for next layer's scatter
}

// ---------------- pool: g[batch[n]] += h[n] ----------------------------------
__global__ void pool_kernel(const void* __restrict__ batch) {
    int t = blockIdx.x * blockDim.x + threadIdx.x;
    if (t >= N_NODES * 16) return;
    int node = t >> 4;
    int v = t & 15;
    int b = load_idx(batch, node);
    float4 val = *((const float4*)d_h + (size_t)node * 16 + v);
    float* addr = d_g + (size_t)b * 64 + v * 4;
    asm volatile("red.global.add.v4.f32 [%0], {%1, %2, %3, %4};"
                 :: "l"(addr), "f"(val.x), "f"(val.y), "f"(val.z), "f"(val.w)
                 : "memory");
}

// ---------------- head: out = relu(g@fc1+b1) @ fc2 + b2 -----------------------
__global__ void head_kernel(const float* __restrict__ W1, const float* __restrict__ b1,
                            const float* __restrict__ W2, const float* __restrict__ b2,
                            float* __restrict__ out)
{
    __shared__ float W1s[64 * 64];
    __shared__ float W2s[64 * 16];
    __shared__ float b1s[64];
    __shared__ float b2s[16];
    int tid = threadIdx.x;
#pragma unroll
    for (int i = 0; i < 16; i++) W1s[tid + i * 256] = W1[tid + i * 256];
#pragma unroll
    for (int i = 0; i < 4; i++) W2s[tid + i * 256] = W2[tid + i * 256];
    if (tid < 64) b1s[tid] = b1[tid];
    if (tid < 16) b2s[tid] = b2[tid];
    __syncthreads();

    int row = blockIdx.x * 256 + tid;   // graph index (grid=2)
    float gr[64];
#pragma unroll
    for (int k = 0; k < 64; k++) gr[k] = d_g[(size_t)row * 64 + k];
    float oacc[16];
#pragma unroll
    for (int o = 0; o < 16; o++) oacc[o] = b2s[o];

    for (int j = 0; j < 64; j++) {
        float t = b1s[j];
#pragma unroll
        for (int k = 0; k < 64; k++) t += gr[k] * W1s[k * 64 + j];
        t = fmaxf(t, 0.f);
#pragma unroll
        for (int o = 0; o < 16; o++) oacc[o] += t * W2s[j * 16 + o];
    }
#pragma unroll
    for (int o = 0; o < 16; o++) out[(size_t)row * 16 + o] = oacc[o];
}

// =============================================================================
extern "C" void kernel_launch(void* const* d_in, const int* in_sizes, int n_in,
                              void* d_out, int out_size)
{
    const float* x       = (const float*)d_in[0];
    const void*  ei      = d_in[1];
    const void*  batch   = d_in[2];
    const float* enc_W   = (const float*)d_in[3];
    const float* enc_b   = (const float*)d_in[4];
    const float* conv_W1 = (const float*)d_in[5];
    const float* conv_b1 = (const float*)d_in[6];
    const float* conv_W2 = (const float*)d_in[7];
    const float* conv_b2 = (const float*)d_in[8];
    const float* bn_g    = (const float*)d_in[9];
    const float* bn_b    = (const float*)d_in[10];
    const float* fc1_W   = (const float*)d_in[11];
    const float* fc1_b   = (const float*)d_in[12];
    const float* fc2_W   = (const float*)d_in[13];
    const float* fc2_b   = (const float*)d_in[14];
    float* out = (float*)d_out;

    float *h_p, *z_p, *t_p, *sb_p;
    double* acc_p;
    cudaGetSymbolAddress((void**)&h_p, d_h);
    cudaGetSymbolAddress((void**)&z_p, d_z);
    cudaGetSymbolAddress((void**)&t_p, d_t);
    cudaGetSymbolAddress((void**)&acc_p, d_bnacc);
    cudaGetSymbolAddress((void**)&sb_p, d_bnsb);

    const int NB = (N_NODES + 63) / 64;
    const int SCAT_B = (N_EDGES * 16 + 255) / 256;
    const int APPLY_B = (N_NODES * 16 + 255) / 256;

    detect_kernel<<<1, 256>>>((const unsigned int*)ei);
    zero_kernel<<<(N_GRAPHS * IN_CH + 255) / 256, 256>>>();

    // encoder: h = x@enc_W + enc_b ; z = h
    gemm64<NODE_DIM, false, false><<<NB, 256>>>(x, enc_W, enc_b, h_p, z_p,
                                                N_NODES, nullptr);

    for (int l = 0; l < N_LAYERS; l++) {
        scatter_kernel<<<SCAT_B, 256>>>(ei);
        gemm64<IN_CH, true, false><<<NB, 256>>>(z_p, conv_W1 + l * 64 * 64,
                                                conv_b1 + l * 64, t_p, nullptr,
                                                N_NODES, nullptr);
        gemm64<IN_CH, true, true><<<NB, 256>>>(t_p, conv_W2 + l * 64 * 64,
                                               conv_b2 + l * 64, z_p, nullptr,
                                               N_NODES, acc_p + l * 128);
        bn_finalize<<<1, 64>>>(acc_p + l * 128, bn_g + l * 64, bn_b + l * 64,
                               sb_p + l * 128);
        bn_apply<<<APPLY_B, 256>>>(sb_p + l * 128);
    }

    pool_kernel<<<APPLY_B, 256>>>(batch);
    head_kernel<<<2, 256>>>(fc1_W, fc1_b, fc2_W, fc2_b, out);
}

// round 3
// speedup vs baseline: 1.2032x; 1.2032x over previous
#include <cuda_runtime.h>

#define N_NODES 50000
#define N_EDGES 800000
#define NODE_DIM 128
#define IN_CH 64
#define OUT_CH 16
#define N_GRAPHS 512
#define N_LAYERS 5

// ---------------- scratch (device globals; 16B-aligned) ----------------------
__device__ __align__(16) float d_h[N_NODES * IN_CH];   // aggregation output
__device__ __align__(16) float d_z[N_NODES * IN_CH];   // encoder / MLP output
__device__ __align__(16) double d_bnacc[N_LAYERS * 2 * IN_CH];
__device__ __align__(16) float d_g[N_GRAPHS * IN_CH];
__device__ int d_deg[N_NODES];
__device__ int d_rowptr[N_NODES + 1];
__device__ int d_cursor[N_NODES];
__device__ int d_csrsrc[N_EDGES];
__device__ int d_idx64;

// ---------------- dtype sniff: int64 of small values -> odd 32-bit words 0 ---
__global__ void detect_kernel(const unsigned int* __restrict__ ei_words) {
    __shared__ int any_nonzero;
    if (threadIdx.x == 0) any_nonzero = 0;
    __syncthreads();
    unsigned w = ei_words[threadIdx.x * 2 + 1];
    if (w != 0u) atomicOr(&any_nonzero, 1);
    __syncthreads();
    if (threadIdx.x == 0) d_idx64 = (any_nonzero == 0) ? 1 : 0;
}

__device__ __forceinline__ int load_idx(const void* p, long long i) {
    if (d_idx64) return (int)((const long long*)p)[i];
    return ((const int*)p)[i];
}

// ---------------- zero init --------------------------------------------------
__global__ void zero_kernel() {
    int i = blockIdx.x * blockDim.x + threadIdx.x;
    if (i < N_NODES) d_deg[i] = 0;
    if (i < N_GRAPHS * IN_CH) d_g[i] = 0.0f;
    if (i < N_LAYERS * 2 * IN_CH) d_bnacc[i] = 0.0;
}

// ---------------- CSR build --------------------------------------------------
__global__ void count_kernel(const void* __restrict__ ei) {
    int e = blockIdx.x * blockDim.x + threadIdx.x;
    if (e >= N_EDGES) return;
    int dst = load_idx(ei, (long long)N_EDGES + e);
    atomicAdd(&d_deg[dst], 1);
}

// single-block sequential-chunk exclusive scan over d_deg -> d_rowptr/d_cursor
__global__ void scan_kernel() {
    __shared__ int wsum[32];
    __shared__ int s_carry;
    const int t = threadIdx.x, lane = t & 31, wid = t >> 5;
    if (t == 0) s_carry = 0;
    __syncthreads();
    for (int base = 0; base < N_NODES; base += 1024) {
        int i = base + t;
        int v = (i < N_NODES) ? d_deg[i] : 0;
        int x = v;
#pragma unroll
        for (int d = 1; d < 32; d <<= 1) {
            int y = __shfl_up_sync(0xFFFFFFFFu, x, d);
            if (lane >= d) x += y;
        }
        if (lane == 31) wsum[wid] = x;
        __syncthreads();
        if (wid == 0) {
            int y = wsum[lane];
#pragma unroll
            for (int d = 1; d < 32; d <<= 1) {
                int z = __shfl_up_sync(0xFFFFFFFFu, y, d);
                if (lane >= d) y += z;
            }
            wsum[lane] = y;
        }
        __syncthreads();
        int off = s_carry + (wid > 0 ? wsum[wid - 1] : 0);
        int excl = off + x - v;
        if (i < N_NODES) { d_rowptr[i] = excl; d_cursor[i] = excl; }
        __syncthreads();
        if (t == 0) s_carry += wsum[31];
        __syncthreads();
    }
    if (t == 0) d_rowptr[N_NODES] = s_carry;
}

__global__ void fill_kernel(const void* __restrict__ ei) {
    int e = blockIdx.x * blockDim.x + threadIdx.x;
    if (e >= N_EDGES) return;
    int src = load_idx(ei, e);
    int dst = load_idx(ei, (long long)N_EDGES + e);
    int pos = atomicAdd(&d_cursor[dst], 1);
    d_csrsrc[pos] = src;
}

// ---------------- aggregation: h[n] = v[n] + sum_{src->n} v[src] -------------
// v = BN(z) (inline scale/bias) or identity. Warp per node, lane = 2 channels.
template<bool BN>
__global__ void agg_kernel(const float* __restrict__ zin, float* __restrict__ hout,
                           const double* __restrict__ acc,
                           const float* __restrict__ gamma,
                           const float* __restrict__ beta)
{
    __shared__ float s_s[64], s_b[64];
    const int tid = threadIdx.x, lane = tid & 31, w = tid >> 5;
    if (BN) {
        if (tid < 64) {
            double sum = acc[tid], sq = acc[64 + tid];
            float mean = (float)(sum / (double)N_NODES);
            float var = (float)(sq / (double)N_NODES) - mean * mean;
            float sc = gamma[tid] * rsqrtf(var + 1e-5f);
            s_s[tid] = sc;
            s_b[tid] = beta[tid] - mean * sc;
        }
        __syncthreads();
    }
    int node = blockIdx.x * 8 + w;
    if (node >= N_NODES) return;
    const int c0 = lane * 2;
    const float sx = BN ? s_s[c0] : 1.f, sy = BN ? s_s[c0 + 1] : 1.f;
    const float bx = BN ? s_b[c0] : 0.f, by = BN ? s_b[c0 + 1] : 0.f;

    float2 v = *(const float2*)(zin + (size_t)node * 64 + c0);
    float ax = v.x * sx + bx, ay = v.y * sy + by;

    int j = d_rowptr[node];
    const int r1 = d_rowptr[node + 1];
    for (; j + 1 < r1; j += 2) {
        int i0 = d_csrsrc[j], i1 = d_csrsrc[j + 1];
        float2 v0 = *(const float2*)(zin + (size_t)i0 * 64 + c0);
        float2 v1 = *(const float2*)(zin + (size_t)i1 * 64 + c0);
        ax += v0.x * sx + bx; ay += v0.y * sy + by;
        ax += v1.x * sx + bx; ay += v1.y * sy + by;
    }
    if (j < r1) {
        int i0 = d_csrsrc[j];
        float2 v0 = *(const float2*)(zin + (size_t)i0 * 64 + c0);
        ax += v0.x * sx + bx; ay += v0.y * sy + by;
    }
    *(float2*)(hout + (size_t)node * 64 + c0) = make_float2(ax, ay);
}

// ---------------- fused MLP / encoder GEMM -----------------------------------
// FUSED: out = relu(relu(A@W1+b1)@W2+b2), BN-stat accumulate.
// !FUSED (encoder): out = A@W1+b1.
template<int K, bool FUSED>
__global__ void mlp_kernel(const float* __restrict__ A, const float* __restrict__ W1,
                           const float* __restrict__ b1, const float* __restrict__ W2,
                           const float* __restrict__ b2, float* __restrict__ out,
                           double* __restrict__ bnacc)
{
    __shared__ float As[64][66];
    __shared__ float Ws[64][64];
    __shared__ float Wb[64][64];
    __shared__ float ssum[64], ssq[64];

    const int tid = threadIdx.x;
    const int tx = tid & 15;
    const int ty = tid >> 4;
    const int row0 = blockIdx.x * 64;

    if (FUSED) {
#pragma unroll
        for (int i = 0; i < 4; i++) {
            int f = tid + i * 256;
            int wr = f >> 4, c4 = f & 15;
            *(float4*)(&Wb[wr][c4 * 4]) = *(const float4*)(W2 + wr * 64 + c4 * 4);
        }
    }

    float acc[4][4] = {};
    for (int kc = 0; kc < K / 64; kc++) {
#pragma unroll
        for (int i = 0; i < 4; i++) {
            int f = tid + i * 256;
            int r = f >> 4, c4 = f & 15;
            int gr = row0 + r;
            float4 v = make_float4(0.f, 0.f, 0.f, 0.f);
            if (gr < N_NODES)
                v = *(const float4*)(A + (size_t)gr * K + kc * 64 + c4 * 4);
            As[r][c4 * 4 + 0] = v.x;
            As[r][c4 * 4 + 1] = v.y;
            As[r][c4 * 4 + 2] = v.z;
            As[r][c4 * 4 + 3] = v.w;
        }
#pragma unroll
        for (int i = 0; i < 4; i++) {
            int f = tid + i * 256;
            int wr = f >> 4, c4 = f & 15;
            *(float4*)(&Ws[wr][c4 * 4]) =
                *(const float4*)(W1 + (size_t)(kc * 64 + wr) * 64 + c4 * 4);
        }
        __syncthreads();
#pragma unroll 8
        for (int k = 0; k < 64; k++) {
            float4 wv = *(const float4*)(&Ws[k][tx * 4]);
#pragma unroll
            for (int i = 0; i < 4; i++) {
                float a = As[ty * 4 + i][k];
                acc[i][0] += a * wv.x;
                acc[i][1] += a * wv.y;
                acc[i][2] += a * wv.z;
                acc[i][3] += a * wv.w;
            }
        }
        __syncthreads();
    }

    float4 bv = *(const float4*)(b1 + tx * 4);

    if (!FUSED) {
        // encoder epilogue: linear only
#pragma unroll
        for (int i = 0; i < 4; i++) {
            int gr = row0 + ty * 4 + i;
            if (gr < N_NODES) {
                float4 o;
                o.x = acc[i][0] + bv.x; o.y = acc[i][1] + bv.y;
                o.z = acc[i][2] + bv.z; o.w = acc[i][3] + bv.w;
                *(float4*)(out + (size_t)gr * 64 + tx * 4) = o;
            }
        }
        return;
    }

    // T = relu(acc + b1) -> As (safe: last op above was __syncthreads)
#pragma unroll
    for (int i = 0; i < 4; i++) {
        As[ty * 4 + i][tx * 4 + 0] = fmaxf(acc[i][0] + bv.x, 0.f);
        As[ty * 4 + i][tx * 4 + 1] = fmaxf(acc[i][1] + bv.y, 0.f);
        As[ty * 4 + i][tx * 4 + 2] = fmaxf(acc[i][2] + bv.z, 0.f);
        As[ty * 4 + i][tx * 4 + 3] = fmaxf(acc[i][3] + bv.w, 0.f);
    }
    __syncthreads();

    float acc2[4][4] = {};
#pragma unroll 8
    for (int k = 0; k < 64; k++) {
        float4 wv = *(const float4*)(&Wb[k][tx * 4]);
#pragma unroll
        for (int i = 0; i < 4; i++) {
            float a = As[ty * 4 + i][k];
            acc2[i][0] += a * wv.x;
            acc2[i][1] += a * wv.y;
            acc2[i][2] += a * wv.z;
            acc2[i][3] += a * wv.w;
        }
    }

    float4 bv2 = *(const float4*)(b2 + tx * 4);
    float csum[4] = {0.f, 0.f, 0.f, 0.f};
    float csq[4] = {0.f, 0.f, 0.f, 0.f};
#pragma unroll
    for (int i = 0; i < 4; i++) {
        int gr = row0 + ty * 4 + i;
        float4 o;
        o.x = fmaxf(acc2[i][0] + bv2.x, 0.f);
        o.y = fmaxf(acc2[i][1] + bv2.y, 0.f);
        o.z = fmaxf(acc2[i][2] + bv2.z, 0.f);
        o.w = fmaxf(acc2[i][3] + bv2.w, 0.f);
        if (gr < N_NODES) {
            *(float4*)(out + (size_t)gr * 64 + tx * 4) = o;
            csum[0] += o.x; csum[1] += o.y; csum[2] += o.z; csum[3] += o.w;
            csq[0] += o.x * o.x; csq[1] += o.y * o.y;
            csq[2] += o.z * o.z; csq[3] += o.w * o.w;
        }
    }

    if (tid < 64) { ssum[tid] = 0.f; ssq[tid] = 0.f; }
    __syncthreads();
#pragma unroll
    for (int j = 0; j < 4; j++) {
        atomicAdd(&ssum[tx * 4 + j], csum[j]);
        atomicAdd(&ssq[tx * 4 + j], csq[j]);
    }
    __syncthreads();
    if (tid < 64) {
        atomicAdd(&bnacc[tid], (double)ssum[tid]);
        atomicAdd(&bnacc[64 + tid], (double)ssq[tid]);
    }
}

// ---------------- pool: g[batch[n]] += BN(z[n]) ------------------------------
__global__ void pool_kernel(const void* __restrict__ batch,
                            const double* __restrict__ acc,
                            const float* __restrict__ gamma,
                            const float* __restrict__ beta)
{
    __shared__ float s_s[64], s_b[64];
    const int tid = threadIdx.x, lane = tid & 31, w = tid >> 5;
    if (tid < 64) {
        double sum = acc[tid], sq = acc[64 + tid];
        float mean = (float)(sum / (double)N_NODES);
        float var = (float)(sq / (double)N_NODES) - mean * mean;
        float sc = gamma[tid] * rsqrtf(var + 1e-5f);
        s_s[tid] = sc;
        s_b[tid] = beta[tid] - mean * sc;
    }
    __syncthreads();
    int node = blockIdx.x * 8 + w;
    if (node >= N_NODES) return;
    const int c0 = lane * 2;
    int b = load_idx(batch, node);
    float2 v = *(const float2*)(d_z + (size_t)node * 64 + c0);
    float vx = v.x * s_s[c0] + s_b[c0];
    float vy = v.y * s_s[c0 + 1] + s_b[c0 + 1];
    float* addr = d_g + (size_t)b * 64 + c0;
    asm volatile("red.global.add.v2.f32 [%0], {%1, %2};"
                 :: "l"(addr), "f"(vx), "f"(vy) : "memory");
}

// ---------------- head: out = relu(g@fc1+b1) @ fc2 + b2 ----------------------
__global__ void head_kernel(const float* __restrict__ W1, const float* __restrict__ b1,
                            const float* __restrict__ W2, const float* __restrict__ b2,
                            float* __restrict__ out)
{
    __shared__ float W1s[64 * 64];
    __shared__ float W2s[64 * 16];
    __shared__ float b1s[64];
    __shared__ float b2s[16];
    int tid = threadIdx.x;
#pragma unroll
    for (int i = 0; i < 16; i++) W1s[tid + i * 256] = W1[tid + i * 256];
#pragma unroll
    for (int i = 0; i < 4; i++) W2s[tid + i * 256] = W2[tid + i * 256];
    if (tid < 64) b1s[tid] = b1[tid];
    if (tid < 16) b2s[tid] = b2[tid];
    __syncthreads();

    int row = blockIdx.x * 256 + tid;
    float gr[64];
#pragma unroll
    for (int k = 0; k < 64; k++) gr[k] = d_g[(size_t)row * 64 + k];
    float oacc[16];
#pragma unroll
    for (int o = 0; o < 16; o++) oacc[o] = b2s[o];

    for (int j = 0; j < 64; j++) {
        float t = b1s[j];
#pragma unroll
        for (int k = 0; k < 64; k++) t += gr[k] * W1s[k * 64 + j];
        t = fmaxf(t, 0.f);
#pragma unroll
        for (int o = 0; o < 16; o++) oacc[o] += t * W2s[j * 16 + o];
    }
#pragma unroll
    for (int o = 0; o < 16; o++) out[(size_t)row * 16 + o] = oacc[o];
}

// =============================================================================
extern "C" void kernel_launch(void* const* d_in, const int* in_sizes, int n_in,
                              void* d_out, int out_size)
{
    const float* x       = (const float*)d_in[0];
    const void*  ei      = d_in[1];
    const void*  batch   = d_in[2];
    const float* enc_W   = (const float*)d_in[3];
    const float* enc_b   = (const float*)d_in[4];
    const float* conv_W1 = (const float*)d_in[5];
    const float* conv_b1 = (const float*)d_in[6];
    const float* conv_W2 = (const float*)d_in[7];
    const float* conv_b2 = (const float*)d_in[8];
    const float* bn_g    = (const float*)d_in[9];
    const float* bn_b    = (const float*)d_in[10];
    const float* fc1_W   = (const float*)d_in[11];
    const float* fc1_b   = (const float*)d_in[12];
    const float* fc2_W   = (const float*)d_in[13];
    const float* fc2_b   = (const float*)d_in[14];
    float* out = (float*)d_out;

    float *h_p, *z_p;
    double* acc_p;
    cudaGetSymbolAddress((void**)&h_p, d_h);
    cudaGetSymbolAddress((void**)&z_p, d_z);
    cudaGetSymbolAddress((void**)&acc_p, d_bnacc);

    const int NB = (N_NODES + 63) / 64;            // 782
    const int EB = (N_EDGES + 255) / 256;          // 3125
    const int WB = (N_NODES + 7) / 8;              // 6250 (warp per node)

    detect_kernel<<<1, 256>>>((const unsigned int*)ei);
    zero_kernel<<<(N_NODES + 255) / 256, 256>>>();

    // CSR build
    count_kernel<<<EB, 256>>>(ei);
    scan_kernel<<<1, 1024>>>();
    fill_kernel<<<EB, 256>>>(ei);

    // encoder: z = x@enc_W + enc_b
    mlp_kernel<NODE_DIM, false><<<NB, 256>>>(x, enc_W, enc_b, nullptr, nullptr,
                                             z_p, nullptr);

    for (int l = 0; l < N_LAYERS; l++) {
        if (l == 0)
            agg_kernel<false><<<WB, 256>>>(z_p, h_p, nullptr, nullptr, nullptr);
        else
            agg_kernel<true><<<WB, 256>>>(z_p, h_p, acc_p + (l - 1) * 128,
                                          bn_g + (l - 1) * 64, bn_b + (l - 1) * 64);
        mlp_kernel<IN_CH, true><<<NB, 256>>>(h_p, conv_W1 + l * 64 * 64,
                                             conv_b1 + l * 64,
                                             conv_W2 + l * 64 * 64,
                                             conv_b2 + l * 64,
                                             z_p, acc_p + l * 128);
    }

    // pool (BN of last layer applied inline) + head
    pool_kernel<<<WB, 256>>>(batch, acc_p + 4 * 128, bn_g + 4 * 64, bn_b + 4 * 64);
    head_kernel<<<2, 256>>>(fc1_W, fc1_b, fc2_W, fc2_b, out);
}